// round 2
// baseline (speedup 1.0000x reference)
#include <cuda_runtime.h>
#include <math.h>

// ---------------------------------------------------------------------------
// MoE block: top-2 router (vmoe-style, deterministic, capacity) + grouped MLP
//   det stream: 8 groups x 1024 tokens, capacity 256
//   cls stream: 8 groups x  128 tokens, capacity  32
// Expert row space: per expert 2304 rows = 8*256 (det) + 8*32 (cls).
// ---------------------------------------------------------------------------

#define NEXP 8
#define DM 768
#define MLPD 3072
#define CAP_DET 256
#define CAP_CLS 32
#define RPE 2304                 // rows per expert
#define MTOT (NEXP * RPE)        // 18432 total gathered rows
#define NTOK_DET 8192
#define NTOK_CLS 1024
#define NTOK (NTOK_DET + NTOK_CLS)

// --------------------------- scratch (device globals) ----------------------
__device__ float g_xg[(size_t)MTOT * DM];     // gathered expert inputs
__device__ float g_h [(size_t)MTOT * MLPD];   // hidden activations
__device__ float g_ye[(size_t)MTOT * DM];     // expert outputs
__device__ int   g_row_src[MTOT];             // source token per expert row (-1 empty)
__device__ signed char g_tok_e[NTOK][2];      // top-2 expert ids per token
__device__ float g_tok_p[NTOK][2];            // top-2 gate values per token
__device__ int   g_tok_rows[NTOK][2];         // kept row in expert space (-1 dropped)
__device__ float g_tok_g[NTOK][2];            // kept gate (combine weight)

__device__ __forceinline__ float gelu_tanh(float x) {
    float x3 = x * x * x;
    return 0.5f * x * (1.0f + tanhf(0.7978845608028654f * (x + 0.044715f * x3)));
}

// --------------------------- init -----------------------------------------
__global__ void init_kernel() {
    int i = blockIdx.x * blockDim.x + threadIdx.x;
    if (i < MTOT) g_row_src[i] = -1;
    if (i < NTOK * 2) {
        ((int*)g_tok_rows)[i] = -1;
        ((float*)g_tok_g)[i] = 0.0f;
    }
}

// --------------------------- router: warp per token ------------------------
__global__ void router_kernel(const float* __restrict__ x,
                              const float* __restrict__ wr,
                              int n_tokens, int tok_base) {
    int gwarp = (blockIdx.x * blockDim.x + threadIdx.x) >> 5;
    int lane  = threadIdx.x & 31;
    if (gwarp >= n_tokens) return;
    const float* xr = x + (size_t)gwarp * DM;

    float acc[NEXP];
#pragma unroll
    for (int e = 0; e < NEXP; e++) acc[e] = 0.f;
    for (int d = lane; d < DM; d += 32) {
        float xv = xr[d];
        const float* w = wr + d * NEXP;
#pragma unroll
        for (int e = 0; e < NEXP; e++) acc[e] += xv * w[e];
    }
#pragma unroll
    for (int e = 0; e < NEXP; e++) {
#pragma unroll
        for (int off = 16; off > 0; off >>= 1)
            acc[e] += __shfl_xor_sync(0xffffffffu, acc[e], off);
    }
    if (lane == 0) {
        float mx = acc[0];
#pragma unroll
        for (int e = 1; e < NEXP; e++) mx = fmaxf(mx, acc[e]);
        float p[NEXP];
        float s = 0.f;
#pragma unroll
        for (int e = 0; e < NEXP; e++) { p[e] = expf(acc[e] - mx); s += p[e]; }
        float inv = 1.0f / s;
        // top-2, lowest index wins ties (matches jax.lax.top_k)
        int e0 = 0;
#pragma unroll
        for (int e = 1; e < NEXP; e++) if (p[e] > p[e0]) e0 = e;
        int e1 = (e0 == 0) ? 1 : 0;
#pragma unroll
        for (int e = 0; e < NEXP; e++) if (e != e0 && p[e] > p[e1]) e1 = e;
        int t = tok_base + gwarp;
        g_tok_e[t][0] = (signed char)e0;
        g_tok_e[t][1] = (signed char)e1;
        g_tok_p[t][0] = p[e0] * inv;
        g_tok_p[t][1] = p[e1] * inv;
    }
}

// ------------------ positions: rank-major cumsum + capacity -----------------
// One block per group; warp e scans the 2S assignments (rank-0 tokens in order,
// then rank-1 tokens) counting matches for expert e via ballot prefix sums.
__global__ void positions_kernel(int S, int C, int tok_base, int row_off) {
    __shared__ signed char se0[1024], se1[1024];
    __shared__ float sg0[1024], sg1[1024];
    int g = blockIdx.x;
    int tid = threadIdx.x;
    for (int t = tid; t < S; t += blockDim.x) {
        int gt = tok_base + g * S + t;
        se0[t] = g_tok_e[gt][0];
        se1[t] = g_tok_e[gt][1];
        sg0[t] = g_tok_p[gt][0];
        sg1[t] = g_tok_p[gt][1];
    }
    __syncthreads();

    int e = tid >> 5;       // expert handled by this warp (0..7)
    int lane = tid & 31;
    int base = 0;
    int total = 2 * S;
    for (int j0 = 0; j0 < total; j0 += 32) {
        int j = j0 + lane;
        int exp_j = -1;
        if (j < total) exp_j = (j < S) ? (int)se0[j] : (int)se1[j - S];
        bool m = (exp_j == e);
        unsigned mask = __ballot_sync(0xffffffffu, m);
        if (m) {
            int pos = base + __popc(mask & ((1u << lane) - 1u));
            if (pos < C) {
                int t = (j < S) ? j : (j - S);
                int r = (j < S) ? 0 : 1;
                int gt = tok_base + g * S + t;
                float gate = (r == 0) ? sg0[t] : sg1[t];
                int row = e * RPE + row_off + g * C + pos;
                g_row_src[row] = gt;
                g_tok_rows[gt][r] = row;
                g_tok_g[gt][r] = gate;
            }
        }
        base += __popc(mask);
    }
}

// --------------------------- gather (zero-fill empties) ---------------------
__global__ void gather_kernel(const float* __restrict__ xdet,
                              const float* __restrict__ xcls) {
    int row = blockIdx.x;
    int i = threadIdx.x;                 // 192 threads * float4 = 768
    int src = g_row_src[row];
    float4 v = make_float4(0.f, 0.f, 0.f, 0.f);
    if (src >= 0) {
        const float* xp = (src < NTOK_DET)
            ? (xdet + (size_t)src * DM)
            : (xcls + (size_t)(src - NTOK_DET) * DM);
        v = ((const float4*)xp)[i];
    }
    ((float4*)(g_xg + (size_t)row * DM))[i] = v;
}

// --------------------------- SGEMM 128x128x8, 8x8/thread --------------------
template<int K, int N, bool GELU>
__device__ __forceinline__ void sgemm_body(const float* __restrict__ A,
                                           const float* __restrict__ W,
                                           const float* __restrict__ bias,
                                           float* __restrict__ C) {
    __shared__ __align__(16) float As[8][128];
    __shared__ __align__(16) float Bs[8][128];
    int bx = blockIdx.x, by = blockIdx.y;
    int tid = threadIdx.x;
    int expert = (by * 128) / RPE;       // RPE % 128 == 0 -> tiles never straddle
    const float* Ab = A + (size_t)by * 128 * K;
    const float* Wb = W + (size_t)expert * K * N + bx * 128;

    int aRow = tid >> 1, aCol = (tid & 1) * 4;
    int bRow = tid >> 5, bCol = (tid & 31) * 4;
    int tRow = (tid >> 4) * 8, tCol = (tid & 15) * 8;

    float acc[8][8];
#pragma unroll
    for (int i = 0; i < 8; i++)
#pragma unroll
        for (int j = 0; j < 8; j++) acc[i][j] = 0.f;

    for (int k0 = 0; k0 < K; k0 += 8) {
        float4 av = *(const float4*)(Ab + (size_t)aRow * K + k0 + aCol);
        As[aCol + 0][aRow] = av.x;
        As[aCol + 1][aRow] = av.y;
        As[aCol + 2][aRow] = av.z;
        As[aCol + 3][aRow] = av.w;
        *(float4*)&Bs[bRow][bCol] =
            *(const float4*)(Wb + (size_t)(k0 + bRow) * N + bCol);
        __syncthreads();
#pragma unroll
        for (int kk = 0; kk < 8; kk++) {
            float ra[8], rb[8];
            *(float4*)&ra[0] = *(const float4*)&As[kk][tRow];
            *(float4*)&ra[4] = *(const float4*)&As[kk][tRow + 4];
            *(float4*)&rb[0] = *(const float4*)&Bs[kk][tCol];
            *(float4*)&rb[4] = *(const float4*)&Bs[kk][tCol + 4];
#pragma unroll
            for (int i = 0; i < 8; i++)
#pragma unroll
                for (int j = 0; j < 8; j++)
                    acc[i][j] = fmaf(ra[i], rb[j], acc[i][j]);
        }
        __syncthreads();
    }

    float bv[8];
#pragma unroll
    for (int j = 0; j < 8; j++) bv[j] = bias[expert * N + bx * 128 + tCol + j];
#pragma unroll
    for (int i = 0; i < 8; i++) {
        float tmp[8];
#pragma unroll
        for (int j = 0; j < 8; j++) {
            float v = acc[i][j] + bv[j];
            tmp[j] = GELU ? gelu_tanh(v) : v;
        }
        float* crow = C + (size_t)(by * 128 + tRow + i) * N + bx * 128 + tCol;
        *(float4*)(crow + 0) = make_float4(tmp[0], tmp[1], tmp[2], tmp[3]);
        *(float4*)(crow + 4) = make_float4(tmp[4], tmp[5], tmp[6], tmp[7]);
    }
}

__global__ __launch_bounds__(256)
void gemm1_kernel(const float* __restrict__ w1, const float* __restrict__ b1) {
    sgemm_body<DM, MLPD, true>(g_xg, w1, b1, g_h);
}

__global__ __launch_bounds__(256)
void gemm2_kernel(const float* __restrict__ w2, const float* __restrict__ b2) {
    sgemm_body<MLPD, DM, false>(g_h, w2, b2, g_ye);
}

// --------------------------- scatter (combine) ------------------------------
__global__ void scatter_kernel(float* __restrict__ out) {
    int t = blockIdx.x;                  // token index; det rows then cls rows
    int i = threadIdx.x;                 // 192 threads * float4 = 768
    int r0 = g_tok_rows[t][0];
    int r1 = g_tok_rows[t][1];
    float ga = g_tok_g[t][0];
    float gb = g_tok_g[t][1];
    float4 acc = make_float4(0.f, 0.f, 0.f, 0.f);
    if (r0 >= 0) {
        float4 v = ((const float4*)(g_ye + (size_t)r0 * DM))[i];
        acc.x = ga * v.x; acc.y = ga * v.y; acc.z = ga * v.z; acc.w = ga * v.w;
    }
    if (r1 >= 0) {
        float4 v = ((const float4*)(g_ye + (size_t)r1 * DM))[i];
        acc.x += gb * v.x; acc.y += gb * v.y; acc.z += gb * v.z; acc.w += gb * v.w;
    }
    // out layout: det tokens occupy [0, 8192*768), cls directly after -> t*768 works
    ((float4*)(out + (size_t)t * DM))[i] = acc;
}

// --------------------------- launch -----------------------------------------
extern "C" void kernel_launch(void* const* d_in, const int* in_sizes, int n_in,
                              void* d_out, int out_size) {
    (void)in_sizes; (void)n_in; (void)out_size;
    const float* xdet = (const float*)d_in[0];
    const float* xcls = (const float*)d_in[1];
    const float* wrd  = (const float*)d_in[2];
    const float* wrc  = (const float*)d_in[3];
    const float* w1   = (const float*)d_in[4];
    const float* b1   = (const float*)d_in[5];
    const float* w2   = (const float*)d_in[6];
    const float* b2   = (const float*)d_in[7];
    float* out = (float*)d_out;

    init_kernel<<<(MTOT + 255) / 256, 256>>>();
    router_kernel<<<(NTOK_DET * 32 + 255) / 256, 256>>>(xdet, wrd, NTOK_DET, 0);
    router_kernel<<<(NTOK_CLS * 32 + 255) / 256, 256>>>(xcls, wrc, NTOK_CLS, NTOK_DET);
    positions_kernel<<<8, 256>>>(1024, CAP_DET, 0, 0);
    positions_kernel<<<8, 256>>>(128, CAP_CLS, NTOK_DET, 2048);
    gather_kernel<<<MTOT, 192>>>(xdet, xcls);
    gemm1_kernel<<<dim3(MLPD / 128, MTOT / 128), 256>>>(w1, b1);
    gemm2_kernel<<<dim3(DM / 128, MTOT / 128), 256>>>(w2, b2);
    scatter_kernel<<<NTOK, 192>>>(out);
}

// round 4
// speedup vs baseline: 3.2834x; 3.2834x over previous
#include <cuda_runtime.h>
#include <math.h>
#include <stdint.h>

// ---------------------------------------------------------------------------
// MoE block via mma.sync tf32 (base-target tensor cores; tcgen05 unavailable
// because the harness assembles PTX for .target sm_103, not sm_103a).
//   det: 8 groups x 1024 tokens, cap 256 ; cls: 8 groups x 128 tokens, cap 32
//   GEMM1: [18432,768]x[768,3072]+GELU ; GEMM2: [18432,3072]x[3072,768]
// ---------------------------------------------------------------------------

#define NEXP 8
#define DM 768
#define MLPD 3072
#define CAP_DET 256
#define CAP_CLS 32
#define RPE 2304
#define MTOT (NEXP * RPE)
#define NTOK_DET 8192
#define NTOK_CLS 1024
#define NTOK (NTOK_DET + NTOK_CLS)

#define CHUNK 32                       // K floats per pipeline stage
#define SSTRIDE 36                     // padded smem row stride (floats)
#define TILE_FLOATS (128 * SSTRIDE)    // 4608 floats per operand tile
#define STAGE_FLOATS (2 * TILE_FLOATS) // A + B
#define SMEM_DYN (2 * STAGE_FLOATS * 4)  // double buffered: 73728 bytes

// --------------------------- scratch ---------------------------------------
__device__ float g_xg[(size_t)MTOT * DM];
__device__ float g_h [(size_t)MTOT * MLPD];
__device__ float g_ye[(size_t)MTOT * DM];
__device__ float g_w1t[(size_t)NEXP * MLPD * DM];   // [E, N=3072, K=768]
__device__ float g_w2t[(size_t)NEXP * DM * MLPD];   // [E, N=768,  K=3072]
__device__ int   g_row_src[MTOT];
__device__ signed char g_tok_e[NTOK][2];
__device__ float g_tok_p[NTOK][2];
__device__ int   g_tok_rows[NTOK][2];
__device__ float g_tok_g[NTOK][2];

// --------------------------- helpers ---------------------------------------
__device__ __forceinline__ uint32_t smem_u32(const void* p) {
    uint32_t a;
    asm("{ .reg .u64 t; cvta.to.shared.u64 t, %1; cvt.u32.u64 %0, t; }"
        : "=r"(a) : "l"(p));
    return a;
}
__device__ __forceinline__ void cp_async16(uint32_t sdst, const void* gsrc) {
    asm volatile("cp.async.cg.shared.global [%0], [%1], 16;"
                 :: "r"(sdst), "l"(gsrc) : "memory");
}
__device__ __forceinline__ void cp_commit() {
    asm volatile("cp.async.commit_group;" ::: "memory");
}
template<int N>
__device__ __forceinline__ void cp_wait() {
    asm volatile("cp.async.wait_group %0;" :: "n"(N) : "memory");
}
__device__ __forceinline__ void mma_tf32(float* d, const uint32_t* a,
                                         const uint32_t* b) {
    asm volatile(
        "mma.sync.aligned.m16n8k8.row.col.f32.tf32.tf32.f32 "
        "{%0,%1,%2,%3}, {%4,%5,%6,%7}, {%8,%9}, {%0,%1,%2,%3};"
        : "+f"(d[0]), "+f"(d[1]), "+f"(d[2]), "+f"(d[3])
        : "r"(a[0]), "r"(a[1]), "r"(a[2]), "r"(a[3]),
          "r"(b[0]), "r"(b[1]));
}
__device__ __forceinline__ float to_tf32(float x) {
    float r;
    asm("cvt.rna.tf32.f32 %0, %1;" : "=f"(r) : "f"(x));
    return r;
}
__device__ __forceinline__ float gelu_tanh(float x) {
    float x3 = x * x * x;
    return 0.5f * x * (1.0f + tanhf(0.7978845608028654f * (x + 0.044715f * x3)));
}

// --------------------------- init ------------------------------------------
__global__ void init_kernel() {
    int i = blockIdx.x * blockDim.x + threadIdx.x;
    if (i < MTOT) g_row_src[i] = -1;
    if (i < NTOK * 2) {
        ((int*)g_tok_rows)[i] = -1;
        ((float*)g_tok_g)[i] = 0.0f;
    }
}

// --------------------------- router ----------------------------------------
__global__ void router_kernel(const float* __restrict__ x,
                              const float* __restrict__ wr,
                              int n_tokens, int tok_base) {
    int gwarp = (blockIdx.x * blockDim.x + threadIdx.x) >> 5;
    int lane  = threadIdx.x & 31;
    if (gwarp >= n_tokens) return;
    const float* xr = x + (size_t)gwarp * DM;
    float acc[NEXP];
#pragma unroll
    for (int e = 0; e < NEXP; e++) acc[e] = 0.f;
    for (int d = lane; d < DM; d += 32) {
        float xv = xr[d];
        const float* w = wr + d * NEXP;
#pragma unroll
        for (int e = 0; e < NEXP; e++) acc[e] += xv * w[e];
    }
#pragma unroll
    for (int e = 0; e < NEXP; e++) {
#pragma unroll
        for (int off = 16; off > 0; off >>= 1)
            acc[e] += __shfl_xor_sync(0xffffffffu, acc[e], off);
    }
    if (lane == 0) {
        float mx = acc[0];
#pragma unroll
        for (int e = 1; e < NEXP; e++) mx = fmaxf(mx, acc[e]);
        float p[NEXP]; float s = 0.f;
#pragma unroll
        for (int e = 0; e < NEXP; e++) { p[e] = expf(acc[e] - mx); s += p[e]; }
        float inv = 1.0f / s;
        int e0 = 0;
#pragma unroll
        for (int e = 1; e < NEXP; e++) if (p[e] > p[e0]) e0 = e;
        int e1 = (e0 == 0) ? 1 : 0;
#pragma unroll
        for (int e = 0; e < NEXP; e++) if (e != e0 && p[e] > p[e1]) e1 = e;
        int t = tok_base + gwarp;
        g_tok_e[t][0] = (signed char)e0;
        g_tok_e[t][1] = (signed char)e1;
        g_tok_p[t][0] = p[e0] * inv;
        g_tok_p[t][1] = p[e1] * inv;
    }
}

// ------------------ positions (rank-major cumsum + capacity) ----------------
__global__ void positions_kernel(int S, int C, int tok_base, int row_off) {
    __shared__ signed char se0[1024], se1[1024];
    __shared__ float sg0[1024], sg1[1024];
    int g = blockIdx.x;
    int tid = threadIdx.x;
    for (int t = tid; t < S; t += blockDim.x) {
        int gt = tok_base + g * S + t;
        se0[t] = g_tok_e[gt][0];
        se1[t] = g_tok_e[gt][1];
        sg0[t] = g_tok_p[gt][0];
        sg1[t] = g_tok_p[gt][1];
    }
    __syncthreads();
    int e = tid >> 5;
    int lane = tid & 31;
    int base = 0;
    int total = 2 * S;
    for (int j0 = 0; j0 < total; j0 += 32) {
        int j = j0 + lane;
        int exp_j = -1;
        if (j < total) exp_j = (j < S) ? (int)se0[j] : (int)se1[j - S];
        bool m = (exp_j == e);
        unsigned mask = __ballot_sync(0xffffffffu, m);
        if (m) {
            int pos = base + __popc(mask & ((1u << lane) - 1u));
            if (pos < C) {
                int t = (j < S) ? j : (j - S);
                int r = (j < S) ? 0 : 1;
                int gt = tok_base + g * S + t;
                float gate = (r == 0) ? sg0[t] : sg1[t];
                int row = e * RPE + row_off + g * C + pos;
                g_row_src[row] = gt;
                g_tok_rows[gt][r] = row;
                g_tok_g[gt][r] = gate;
            }
        }
        base += __popc(mask);
    }
}

// --------------------------- weight transpose (+tf32 rounding) --------------
__global__ void transpose_kernel(const float* __restrict__ src,
                                 float* __restrict__ dst, int K, int N) {
    __shared__ float tile[32][33];
    int e = blockIdx.z;
    int n0 = blockIdx.x * 32, k0 = blockIdx.y * 32;
    int tx = threadIdx.x, ty = threadIdx.y;
    const float* S = src + (size_t)e * K * N;
    float* D = dst + (size_t)e * N * K;
#pragma unroll
    for (int r = 0; r < 32; r += 8)
        tile[ty + r][tx] = S[(size_t)(k0 + ty + r) * N + n0 + tx];
    __syncthreads();
#pragma unroll
    for (int r = 0; r < 32; r += 8)
        D[(size_t)(n0 + ty + r) * K + k0 + tx] = to_tf32(tile[tx][ty + r]);
}

// --------------------------- gather (+tf32 rounding) -------------------------
__global__ void gather_kernel(const float* __restrict__ xdet,
                              const float* __restrict__ xcls) {
    int row = blockIdx.x;
    int i = threadIdx.x;
    int src = g_row_src[row];
    float4 v = make_float4(0.f, 0.f, 0.f, 0.f);
    if (src >= 0) {
        const float* xp = (src < NTOK_DET)
            ? (xdet + (size_t)src * DM)
            : (xcls + (size_t)(src - NTOK_DET) * DM);
        v = ((const float4*)xp)[i];
        v.x = to_tf32(v.x); v.y = to_tf32(v.y);
        v.z = to_tf32(v.z); v.w = to_tf32(v.w);
    }
    ((float4*)(g_xg + (size_t)row * DM))[i] = v;
}

// --------------------------- mma.sync tf32 GEMM ------------------------------
// C[M,NTOT] = A[M,K] * WT[e][NTOT,K]^T  (+bias, optional GELU+tf32 round)
// 128x128 tile, 256 threads (2 M-warps x 4 N-warps, 64x32 per warp),
// K staged in CHUNK=32 slices, cp.async double-buffered.
template<int K, int NTOT, bool GELU>
__device__ __forceinline__ void tc_gemm(const float* __restrict__ A,
                                        const float* __restrict__ WT,
                                        const float* __restrict__ bias,
                                        float* __restrict__ C) {
    extern __shared__ float smem[];
    int tid = threadIdx.x;
    int wid = tid >> 5, lane = tid & 31;
    int gid = lane >> 2, tig = lane & 3;      // mma fragment coords
    int warp_m = wid & 1, warp_n = wid >> 1;  // 2 x 4
    int m_base = warp_m * 64, n_base = warp_n * 32;
    int bx = blockIdx.x, by = blockIdx.y;
    int e = (by * 128) / RPE;                 // RPE % 128 == 0
    const float* Ab = A + (size_t)by * 128 * K;
    const float* Wb = WT + ((size_t)e * NTOT + (size_t)bx * 128) * K;

    float acc[4][4][4];
#pragma unroll
    for (int mi = 0; mi < 4; mi++)
#pragma unroll
        for (int ni = 0; ni < 4; ni++)
#pragma unroll
            for (int q = 0; q < 4; q++) acc[mi][ni][q] = 0.f;

    const int NC = K / CHUNK;
    uint32_t sbase = smem_u32(smem);

    // stage loader: copy A/B chunk c into buffer (c & 1)
    auto issue_stage = [&](int c) {
        int buf = c & 1;
        uint32_t as = sbase + (uint32_t)(buf * STAGE_FLOATS) * 4u;
        uint32_t bs = as + (uint32_t)TILE_FLOATS * 4u;
        int kc = c * CHUNK;
#pragma unroll
        for (int j = 0; j < 4; j++) {
            int idx = j * 256 + tid;          // 1024 float4 per operand
            int row = idx >> 3, q = idx & 7;
            cp_async16(as + (uint32_t)(row * SSTRIDE + q * 4) * 4u,
                       Ab + (size_t)row * K + kc + q * 4);
        }
#pragma unroll
        for (int j = 0; j < 4; j++) {
            int idx = j * 256 + tid;
            int row = idx >> 3, q = idx & 7;
            cp_async16(bs + (uint32_t)(row * SSTRIDE + q * 4) * 4u,
                       Wb + (size_t)row * K + kc + q * 4);
        }
        cp_commit();
    };

    issue_stage(0);
    for (int c = 0; c < NC; c++) {
        if (c + 1 < NC) { issue_stage(c + 1); cp_wait<1>(); }
        else            { cp_wait<0>(); }
        __syncthreads();

        const float* As = smem + (c & 1) * STAGE_FLOATS;
        const float* Bs = As + TILE_FLOATS;
#pragma unroll
        for (int kk = 0; kk < CHUNK; kk += 8) {
            uint32_t afr[4][4];
#pragma unroll
            for (int mi = 0; mi < 4; mi++) {
                const float* ap = As + (m_base + mi * 16 + gid) * SSTRIDE + kk + tig;
                afr[mi][0] = __float_as_uint(ap[0]);
                afr[mi][1] = __float_as_uint(ap[8 * SSTRIDE]);
                afr[mi][2] = __float_as_uint(ap[4]);
                afr[mi][3] = __float_as_uint(ap[8 * SSTRIDE + 4]);
            }
            uint32_t bfr[4][2];
#pragma unroll
            for (int ni = 0; ni < 4; ni++) {
                const float* bp = Bs + (n_base + ni * 8 + gid) * SSTRIDE + kk + tig;
                bfr[ni][0] = __float_as_uint(bp[0]);
                bfr[ni][1] = __float_as_uint(bp[4]);
            }
#pragma unroll
            for (int mi = 0; mi < 4; mi++)
#pragma unroll
                for (int ni = 0; ni < 4; ni++)
                    mma_tf32(acc[mi][ni], afr[mi], bfr[ni]);
        }
        __syncthreads();
    }

    // epilogue: c0,c1 at (r0, cb..cb+1); c2,c3 at (r0+8, cb..cb+1)
#pragma unroll
    for (int ni = 0; ni < 4; ni++) {
        int cb = bx * 128 + n_base + ni * 8 + 2 * tig;
        float b0 = bias[e * NTOT + cb];
        float b1 = bias[e * NTOT + cb + 1];
#pragma unroll
        for (int mi = 0; mi < 4; mi++) {
            int r0 = by * 128 + m_base + mi * 16 + gid;
            float v0 = acc[mi][ni][0] + b0;
            float v1 = acc[mi][ni][1] + b1;
            float v2 = acc[mi][ni][2] + b0;
            float v3 = acc[mi][ni][3] + b1;
            if (GELU) {
                v0 = to_tf32(gelu_tanh(v0)); v1 = to_tf32(gelu_tanh(v1));
                v2 = to_tf32(gelu_tanh(v2)); v3 = to_tf32(gelu_tanh(v3));
            }
            *(float2*)(C + (size_t)r0 * NTOT + cb)       = make_float2(v0, v1);
            *(float2*)(C + (size_t)(r0 + 8) * NTOT + cb) = make_float2(v2, v3);
        }
    }
}

__global__ __launch_bounds__(256)
void gemm1_tc(const float* __restrict__ b1) {
    tc_gemm<DM, MLPD, true>(g_xg, g_w1t, b1, g_h);
}
__global__ __launch_bounds__(256)
void gemm2_tc(const float* __restrict__ b2) {
    tc_gemm<MLPD, DM, false>(g_h, g_w2t, b2, g_ye);
}

// --------------------------- scatter ----------------------------------------
__global__ void scatter_kernel(float* __restrict__ out) {
    int t = blockIdx.x;
    int i = threadIdx.x;
    int r0 = g_tok_rows[t][0];
    int r1 = g_tok_rows[t][1];
    float ga = g_tok_g[t][0];
    float gb = g_tok_g[t][1];
    float4 acc = make_float4(0.f, 0.f, 0.f, 0.f);
    if (r0 >= 0) {
        float4 v = ((const float4*)(g_ye + (size_t)r0 * DM))[i];
        acc.x = ga * v.x; acc.y = ga * v.y; acc.z = ga * v.z; acc.w = ga * v.w;
    }
    if (r1 >= 0) {
        float4 v = ((const float4*)(g_ye + (size_t)r1 * DM))[i];
        acc.x += gb * v.x; acc.y += gb * v.y; acc.z += gb * v.z; acc.w += gb * v.w;
    }
    ((float4*)(out + (size_t)t * DM))[i] = acc;
}

// --------------------------- launch -----------------------------------------
extern "C" void kernel_launch(void* const* d_in, const int* in_sizes, int n_in,
                              void* d_out, int out_size) {
    (void)in_sizes; (void)n_in; (void)out_size;
    const float* xdet = (const float*)d_in[0];
    const float* xcls = (const float*)d_in[1];
    const float* wrd  = (const float*)d_in[2];
    const float* wrc  = (const float*)d_in[3];
    const float* w1   = (const float*)d_in[4];
    const float* b1   = (const float*)d_in[5];
    const float* w2   = (const float*)d_in[6];
    const float* b2   = (const float*)d_in[7];
    float* out = (float*)d_out;

    cudaFuncSetAttribute(gemm1_tc, cudaFuncAttributeMaxDynamicSharedMemorySize, SMEM_DYN);
    cudaFuncSetAttribute(gemm2_tc, cudaFuncAttributeMaxDynamicSharedMemorySize, SMEM_DYN);

    init_kernel<<<(MTOT + 255) / 256, 256>>>();
    {
        float* w1t; cudaGetSymbolAddress((void**)&w1t, g_w1t);
        float* w2t; cudaGetSymbolAddress((void**)&w2t, g_w2t);
        transpose_kernel<<<dim3(MLPD / 32, DM / 32, NEXP), dim3(32, 8)>>>(w1, w1t, DM, MLPD);
        transpose_kernel<<<dim3(DM / 32, MLPD / 32, NEXP), dim3(32, 8)>>>(w2, w2t, MLPD, DM);
    }
    router_kernel<<<(NTOK_DET * 32 + 255) / 256, 256>>>(xdet, wrd, NTOK_DET, 0);
    router_kernel<<<(NTOK_CLS * 32 + 255) / 256, 256>>>(xcls, wrc, NTOK_CLS, NTOK_DET);
    positions_kernel<<<8, 256>>>(1024, CAP_DET, 0, 0);
    positions_kernel<<<8, 256>>>(128, CAP_CLS, NTOK_DET, 2048);
    gather_kernel<<<MTOT, 192>>>(xdet, xcls);
    gemm1_tc<<<dim3(MLPD / 128, MTOT / 128), 256, SMEM_DYN>>>(b1);
    gemm2_tc<<<dim3(DM / 128, MTOT / 128), 256, SMEM_DYN>>>(b2);
    scatter_kernel<<<NTOK, 192>>>(out);
}

// round 5
// speedup vs baseline: 5.8959x; 1.7957x over previous
#include <cuda_runtime.h>
#include <cuda_fp16.h>
#include <math.h>
#include <stdint.h>

// ---------------------------------------------------------------------------
// MoE block via mma.sync fp16 (fp32 accum). fp16 mantissa == tf32 mantissa
// (10 bits) so precision matches the tf32 version while doubling HMMA rate
// and halving operand traffic. tcgen05 unavailable (harness targets sm_103).
// ---------------------------------------------------------------------------

#define NEXP 8
#define DM 768
#define MLPD 3072
#define CAP_DET 256
#define CAP_CLS 32
#define RPE 2304
#define MTOT (NEXP * RPE)
#define NTOK_DET 8192
#define NTOK_CLS 1024
#define NTOK (NTOK_DET + NTOK_CLS)

#define CHUNK 64                        // K halves per pipeline stage (128 B rows)
#define SSTR 72                         // padded smem row stride (halves)
#define TILE_HALVES (128 * SSTR)        // 9216 halves per operand tile
#define STAGE_HALVES (2 * TILE_HALVES)  // A + B
#define SMEM_DYN (2 * STAGE_HALVES * 2) // double buffered: 73728 bytes

// --------------------------- scratch ---------------------------------------
__device__ __half g_xg[(size_t)MTOT * DM];
__device__ __half g_h [(size_t)MTOT * MLPD];
__device__ float  g_ye[(size_t)MTOT * DM];
__device__ __half g_w1t[(size_t)NEXP * MLPD * DM];   // [E, N=3072, K=768]
__device__ __half g_w2t[(size_t)NEXP * DM * MLPD];   // [E, N=768,  K=3072]
__device__ float  g_wrt[2][NEXP * DM];               // router weights [E][D]
__device__ int    g_row_src[MTOT];
__device__ signed char g_tok_e[NTOK][2];
__device__ float  g_tok_p[NTOK][2];
__device__ int    g_tok_rows[NTOK][2];
__device__ float  g_tok_g[NTOK][2];

// --------------------------- helpers ---------------------------------------
__device__ __forceinline__ uint32_t smem_u32(const void* p) {
    uint32_t a;
    asm("{ .reg .u64 t; cvta.to.shared.u64 t, %1; cvt.u32.u64 %0, t; }"
        : "=r"(a) : "l"(p));
    return a;
}
__device__ __forceinline__ void cp_async16(uint32_t sdst, const void* gsrc) {
    asm volatile("cp.async.cg.shared.global [%0], [%1], 16;"
                 :: "r"(sdst), "l"(gsrc) : "memory");
}
__device__ __forceinline__ void cp_commit() {
    asm volatile("cp.async.commit_group;" ::: "memory");
}
template<int N>
__device__ __forceinline__ void cp_wait() {
    asm volatile("cp.async.wait_group %0;" :: "n"(N) : "memory");
}
__device__ __forceinline__ void mma_f16(float* d, const uint32_t* a,
                                        const uint32_t* b) {
    asm volatile(
        "mma.sync.aligned.m16n8k16.row.col.f32.f16.f16.f32 "
        "{%0,%1,%2,%3}, {%4,%5,%6,%7}, {%8,%9}, {%0,%1,%2,%3};"
        : "+f"(d[0]), "+f"(d[1]), "+f"(d[2]), "+f"(d[3])
        : "r"(a[0]), "r"(a[1]), "r"(a[2]), "r"(a[3]),
          "r"(b[0]), "r"(b[1]));
}
__device__ __forceinline__ float gelu_tanh(float x) {
    float x3 = x * x * x;
    return 0.5f * x * (1.0f + tanhf(0.7978845608028654f * (x + 0.044715f * x3)));
}

// --------------------------- init ------------------------------------------
__global__ void init_kernel() {
    int i = blockIdx.x * blockDim.x + threadIdx.x;
    if (i < MTOT) g_row_src[i] = -1;
    if (i < NTOK * 2) {
        ((int*)g_tok_rows)[i] = -1;
        ((float*)g_tok_g)[i] = 0.0f;
    }
}

// ----------------- router weight transpose [D,E] -> [E,D] -------------------
__global__ void wr_transpose_kernel(const float* __restrict__ wr0,
                                    const float* __restrict__ wr1) {
    int i = blockIdx.x * blockDim.x + threadIdx.x;   // 0 .. DM*NEXP-1
    if (i >= DM * NEXP) return;
    int d = i / NEXP, e = i % NEXP;
    g_wrt[0][e * DM + d] = wr0[i];
    g_wrt[1][e * DM + d] = wr1[i];
}

// --------------------------- router ----------------------------------------
__global__ void router_kernel(const float* __restrict__ x,
                              int which, int n_tokens, int tok_base) {
    int gwarp = (blockIdx.x * blockDim.x + threadIdx.x) >> 5;
    int lane  = threadIdx.x & 31;
    if (gwarp >= n_tokens) return;
    const float4* xr = (const float4*)(x + (size_t)gwarp * DM);
    const float* wt = g_wrt[which];

    float acc[NEXP];
#pragma unroll
    for (int e = 0; e < NEXP; e++) acc[e] = 0.f;
#pragma unroll
    for (int it = 0; it < 6; it++) {
        int d4 = it * 32 + lane;
        float4 xv = xr[d4];
#pragma unroll
        for (int e = 0; e < NEXP; e++) {
            float4 wv = ((const float4*)(wt + e * DM))[d4];
            acc[e] += xv.x * wv.x + xv.y * wv.y + xv.z * wv.z + xv.w * wv.w;
        }
    }
#pragma unroll
    for (int e = 0; e < NEXP; e++) {
#pragma unroll
        for (int off = 16; off > 0; off >>= 1)
            acc[e] += __shfl_xor_sync(0xffffffffu, acc[e], off);
    }
    if (lane == 0) {
        float mx = acc[0];
#pragma unroll
        for (int e = 1; e < NEXP; e++) mx = fmaxf(mx, acc[e]);
        float p[NEXP]; float s = 0.f;
#pragma unroll
        for (int e = 0; e < NEXP; e++) { p[e] = expf(acc[e] - mx); s += p[e]; }
        float inv = 1.0f / s;
        int e0 = 0;
#pragma unroll
        for (int e = 1; e < NEXP; e++) if (p[e] > p[e0]) e0 = e;
        int e1 = (e0 == 0) ? 1 : 0;
#pragma unroll
        for (int e = 0; e < NEXP; e++) if (e != e0 && p[e] > p[e1]) e1 = e;
        int t = tok_base + gwarp;
        g_tok_e[t][0] = (signed char)e0;
        g_tok_e[t][1] = (signed char)e1;
        g_tok_p[t][0] = p[e0] * inv;
        g_tok_p[t][1] = p[e1] * inv;
    }
}

// ------------------ positions (rank-major cumsum + capacity) ----------------
__global__ void positions_kernel(int S, int C, int tok_base, int row_off) {
    __shared__ signed char se0[1024], se1[1024];
    __shared__ float sg0[1024], sg1[1024];
    int g = blockIdx.x;
    int tid = threadIdx.x;
    for (int t = tid; t < S; t += blockDim.x) {
        int gt = tok_base + g * S + t;
        se0[t] = g_tok_e[gt][0];
        se1[t] = g_tok_e[gt][1];
        sg0[t] = g_tok_p[gt][0];
        sg1[t] = g_tok_p[gt][1];
    }
    __syncthreads();
    int e = tid >> 5;
    int lane = tid & 31;
    int base = 0;
    int total = 2 * S;
    for (int j0 = 0; j0 < total; j0 += 32) {
        int j = j0 + lane;
        int exp_j = -1;
        if (j < total) exp_j = (j < S) ? (int)se0[j] : (int)se1[j - S];
        bool m = (exp_j == e);
        unsigned mask = __ballot_sync(0xffffffffu, m);
        if (m) {
            int pos = base + __popc(mask & ((1u << lane) - 1u));
            if (pos < C) {
                int t = (j < S) ? j : (j - S);
                int r = (j < S) ? 0 : 1;
                int gt = tok_base + g * S + t;
                float gate = (r == 0) ? sg0[t] : sg1[t];
                int row = e * RPE + row_off + g * C + pos;
                g_row_src[row] = gt;
                g_tok_rows[gt][r] = row;
                g_tok_g[gt][r] = gate;
            }
        }
        base += __popc(mask);
    }
}

// ------------------- weight transpose (fp32 -> half) ------------------------
// src: [E, K, N] row-major -> dst: [E, N, K] half
__global__ void transpose_kernel(const float* __restrict__ src,
                                 __half* __restrict__ dst, int K, int N) {
    __shared__ float tile[32][33];
    int e = blockIdx.z;
    int n0 = blockIdx.x * 32, k0 = blockIdx.y * 32;
    int tx = threadIdx.x, ty = threadIdx.y;
    const float* S = src + (size_t)e * K * N;
    __half* D = dst + (size_t)e * N * K;
#pragma unroll
    for (int r = 0; r < 32; r += 8)
        tile[ty + r][tx] = S[(size_t)(k0 + ty + r) * N + n0 + tx];
    __syncthreads();
#pragma unroll
    for (int r = 0; r < 32; r += 8)
        D[(size_t)(n0 + ty + r) * K + k0 + tx] = __float2half_rn(tile[tx][ty + r]);
}

// --------------------------- gather (fp32 -> half) ---------------------------
__global__ void gather_kernel(const float* __restrict__ xdet,
                              const float* __restrict__ xcls) {
    int row = blockIdx.x;
    int i = threadIdx.x;                 // 192 threads, 4 elems each
    int src = g_row_src[row];
    __half2 h0 = __half2half2(__float2half_rn(0.f));
    __half2 h1 = h0;
    if (src >= 0) {
        const float* xp = (src < NTOK_DET)
            ? (xdet + (size_t)src * DM)
            : (xcls + (size_t)(src - NTOK_DET) * DM);
        float4 v = ((const float4*)xp)[i];
        h0 = __floats2half2_rn(v.x, v.y);
        h1 = __floats2half2_rn(v.z, v.w);
    }
    __half2* dst = (__half2*)(g_xg + (size_t)row * DM) + i * 2;
    dst[0] = h0;
    dst[1] = h1;
}

// --------------------------- mma.sync fp16 GEMM ------------------------------
// C[M,NTOT] = A[M,K] * WT[e][NTOT,K]^T  (+bias fp32, optional GELU)
// 128x128 tile, 256 threads (2 M-warps x 4 N-warps, 64x32 per warp),
// K staged in CHUNK=64-half slices, cp.async double-buffered.
template<int K, int NTOT, bool GELU, typename OutT>
__device__ __forceinline__ void tc_gemm(const __half* __restrict__ A,
                                        const __half* __restrict__ WT,
                                        const float* __restrict__ bias,
                                        OutT* __restrict__ C) {
    extern __shared__ __half smem[];
    int tid = threadIdx.x;
    int wid = tid >> 5, lane = tid & 31;
    int gid = lane >> 2, tig = lane & 3;
    int warp_m = wid & 1, warp_n = wid >> 1;
    int m_base = warp_m * 64, n_base = warp_n * 32;
    int bx = blockIdx.x, by = blockIdx.y;
    int e = (by * 128) / RPE;
    const __half* Ab = A + (size_t)by * 128 * K;
    const __half* Wb = WT + ((size_t)e * NTOT + (size_t)bx * 128) * K;

    float acc[4][4][4];
#pragma unroll
    for (int mi = 0; mi < 4; mi++)
#pragma unroll
        for (int ni = 0; ni < 4; ni++)
#pragma unroll
            for (int q = 0; q < 4; q++) acc[mi][ni][q] = 0.f;

    const int NC = K / CHUNK;
    uint32_t sbase = smem_u32(smem);

    auto issue_stage = [&](int c) {
        int buf = c & 1;
        uint32_t as = sbase + (uint32_t)(buf * STAGE_HALVES) * 2u;
        uint32_t bs = as + (uint32_t)TILE_HALVES * 2u;
        int kc = c * CHUNK;
#pragma unroll
        for (int j = 0; j < 4; j++) {
            int idx = j * 256 + tid;          // 1024 x 16B per operand
            int row = idx >> 3, seg = idx & 7;
            cp_async16(as + (uint32_t)(row * SSTR + seg * 8) * 2u,
                       Ab + (size_t)row * K + kc + seg * 8);
        }
#pragma unroll
        for (int j = 0; j < 4; j++) {
            int idx = j * 256 + tid;
            int row = idx >> 3, seg = idx & 7;
            cp_async16(bs + (uint32_t)(row * SSTR + seg * 8) * 2u,
                       Wb + (size_t)row * K + kc + seg * 8);
        }
        cp_commit();
    };

    issue_stage(0);
    for (int c = 0; c < NC; c++) {
        if (c + 1 < NC) { issue_stage(c + 1); cp_wait<1>(); }
        else            { cp_wait<0>(); }
        __syncthreads();

        const __half* As = smem + (c & 1) * STAGE_HALVES;
        const __half* Bs = As + TILE_HALVES;
#pragma unroll
        for (int kk = 0; kk < CHUNK; kk += 16) {
            uint32_t afr[4][4];
#pragma unroll
            for (int mi = 0; mi < 4; mi++) {
                const __half* ap = As + (m_base + mi * 16 + gid) * SSTR + kk + tig * 2;
                afr[mi][0] = *(const uint32_t*)(ap);
                afr[mi][1] = *(const uint32_t*)(ap + 8 * SSTR);
                afr[mi][2] = *(const uint32_t*)(ap + 8);
                afr[mi][3] = *(const uint32_t*)(ap + 8 * SSTR + 8);
            }
            uint32_t bfr[4][2];
#pragma unroll
            for (int ni = 0; ni < 4; ni++) {
                const __half* bp = Bs + (n_base + ni * 8 + gid) * SSTR + kk + tig * 2;
                bfr[ni][0] = *(const uint32_t*)(bp);
                bfr[ni][1] = *(const uint32_t*)(bp + 8);
            }
#pragma unroll
            for (int mi = 0; mi < 4; mi++)
#pragma unroll
                for (int ni = 0; ni < 4; ni++)
                    mma_f16(acc[mi][ni], afr[mi], bfr[ni]);
        }
        __syncthreads();
    }

#pragma unroll
    for (int ni = 0; ni < 4; ni++) {
        int cb = bx * 128 + n_base + ni * 8 + 2 * tig;
        float b0 = bias[e * NTOT + cb];
        float b1 = bias[e * NTOT + cb + 1];
#pragma unroll
        for (int mi = 0; mi < 4; mi++) {
            int r0 = by * 128 + m_base + mi * 16 + gid;
            float v0 = acc[mi][ni][0] + b0;
            float v1 = acc[mi][ni][1] + b1;
            float v2 = acc[mi][ni][2] + b0;
            float v3 = acc[mi][ni][3] + b1;
            if (GELU) {
                v0 = gelu_tanh(v0); v1 = gelu_tanh(v1);
                v2 = gelu_tanh(v2); v3 = gelu_tanh(v3);
            }
            OutT* p0 = C + (size_t)r0 * NTOT + cb;
            OutT* p1 = C + (size_t)(r0 + 8) * NTOT + cb;
            if (sizeof(OutT) == 2) {
                *(__half2*)p0 = __floats2half2_rn(v0, v1);
                *(__half2*)p1 = __floats2half2_rn(v2, v3);
            } else {
                *(float2*)p0 = make_float2(v0, v1);
                *(float2*)p1 = make_float2(v2, v3);
            }
        }
    }
}

__global__ __launch_bounds__(256)
void gemm1_tc(const float* __restrict__ b1) {
    tc_gemm<DM, MLPD, true, __half>(g_xg, g_w1t, b1, g_h);
}
__global__ __launch_bounds__(256)
void gemm2_tc(const float* __restrict__ b2) {
    tc_gemm<MLPD, DM, false, float>(g_h, g_w2t, b2, g_ye);
}

// --------------------------- scatter ----------------------------------------
__global__ void scatter_kernel(float* __restrict__ out) {
    int t = blockIdx.x;
    int i = threadIdx.x;
    int r0 = g_tok_rows[t][0];
    int r1 = g_tok_rows[t][1];
    float ga = g_tok_g[t][0];
    float gb = g_tok_g[t][1];
    float4 acc = make_float4(0.f, 0.f, 0.f, 0.f);
    if (r0 >= 0) {
        float4 v = ((const float4*)(g_ye + (size_t)r0 * DM))[i];
        acc.x = ga * v.x; acc.y = ga * v.y; acc.z = ga * v.z; acc.w = ga * v.w;
    }
    if (r1 >= 0) {
        float4 v = ((const float4*)(g_ye + (size_t)r1 * DM))[i];
        acc.x += gb * v.x; acc.y += gb * v.y; acc.z += gb * v.z; acc.w += gb * v.w;
    }
    ((float4*)(out + (size_t)t * DM))[i] = acc;
}

// --------------------------- launch -----------------------------------------
extern "C" void kernel_launch(void* const* d_in, const int* in_sizes, int n_in,
                              void* d_out, int out_size) {
    (void)in_sizes; (void)n_in; (void)out_size;
    const float* xdet = (const float*)d_in[0];
    const float* xcls = (const float*)d_in[1];
    const float* wrd  = (const float*)d_in[2];
    const float* wrc  = (const float*)d_in[3];
    const float* w1   = (const float*)d_in[4];
    const float* b1   = (const float*)d_in[5];
    const float* w2   = (const float*)d_in[6];
    const float* b2   = (const float*)d_in[7];
    float* out = (float*)d_out;

    cudaFuncSetAttribute(gemm1_tc, cudaFuncAttributeMaxDynamicSharedMemorySize, SMEM_DYN);
    cudaFuncSetAttribute(gemm2_tc, cudaFuncAttributeMaxDynamicSharedMemorySize, SMEM_DYN);

    init_kernel<<<(MTOT + 255) / 256, 256>>>();
    wr_transpose_kernel<<<(DM * NEXP + 255) / 256, 256>>>(wrd, wrc);
    {
        __half* w1t; cudaGetSymbolAddress((void**)&w1t, g_w1t);
        __half* w2t; cudaGetSymbolAddress((void**)&w2t, g_w2t);
        transpose_kernel<<<dim3(MLPD / 32, DM / 32, NEXP), dim3(32, 8)>>>(w1, w1t, DM, MLPD);
        transpose_kernel<<<dim3(DM / 32, MLPD / 32, NEXP), dim3(32, 8)>>>(w2, w2t, MLPD, DM);
    }
    router_kernel<<<(NTOK_DET * 32 + 255) / 256, 256>>>(xdet, 0, NTOK_DET, 0);
    router_kernel<<<(NTOK_CLS * 32 + 255) / 256, 256>>>(xcls, 1, NTOK_CLS, NTOK_DET);
    positions_kernel<<<8, 256>>>(1024, CAP_DET, 0, 0);
    positions_kernel<<<8, 256>>>(128, CAP_CLS, NTOK_DET, 2048);
    gather_kernel<<<MTOT, 192>>>(xdet, xcls);
    gemm1_tc<<<dim3(MLPD / 128, MTOT / 128), 256, SMEM_DYN>>>(b1);
    gemm2_tc<<<dim3(DM / 128, MTOT / 128), 256, SMEM_DYN>>>(b2);
    scatter_kernel<<<NTOK, 192>>>(out);
}

// round 6
// speedup vs baseline: 6.5043x; 1.1032x over previous
#include <cuda_runtime.h>
#include <cuda_fp16.h>
#include <math.h>
#include <stdint.h>

// ---------------------------------------------------------------------------
// MoE block via mma.sync fp16 (fp32 accum) + ldmatrix fragment loads.
// tcgen05 unavailable (harness assembles for .target sm_103, not sm_103a).
// ---------------------------------------------------------------------------

#define NEXP 8
#define DM 768
#define MLPD 3072
#define CAP_DET 256
#define CAP_CLS 32
#define RPE 2304
#define MTOT (NEXP * RPE)
#define NTOK_DET 8192
#define NTOK_CLS 1024
#define NTOK (NTOK_DET + NTOK_CLS)

#define CHUNK 64                        // K halves per pipeline stage
#define SSTR 72                         // padded smem row stride (halves)
#define TILE_HALVES (128 * SSTR)
#define STAGE_HALVES (2 * TILE_HALVES)
#define SMEM_DYN (2 * STAGE_HALVES * 2) // 73728 bytes

// --------------------------- scratch ---------------------------------------
__device__ __half g_xg[(size_t)MTOT * DM];
__device__ __half g_h [(size_t)MTOT * MLPD];
__device__ float  g_ye[(size_t)MTOT * DM];
__device__ __half g_w1t[(size_t)NEXP * MLPD * DM];   // [E, N=3072, K=768]
__device__ __half g_w2t[(size_t)NEXP * DM * MLPD];   // [E, N=768,  K=3072]
__device__ float  g_wrt[2][NEXP * DM];
__device__ int    g_row_src[MTOT];
__device__ signed char g_tok_e[NTOK][2];
__device__ float  g_tok_p[NTOK][2];
__device__ int    g_tok_rows[NTOK][2];
__device__ float  g_tok_g[NTOK][2];

// --------------------------- helpers ---------------------------------------
__device__ __forceinline__ uint32_t smem_u32(const void* p) {
    uint32_t a;
    asm("{ .reg .u64 t; cvta.to.shared.u64 t, %1; cvt.u32.u64 %0, t; }"
        : "=r"(a) : "l"(p));
    return a;
}
__device__ __forceinline__ void cp_async16(uint32_t sdst, const void* gsrc) {
    asm volatile("cp.async.cg.shared.global [%0], [%1], 16;"
                 :: "r"(sdst), "l"(gsrc) : "memory");
}
__device__ __forceinline__ void cp_commit() {
    asm volatile("cp.async.commit_group;" ::: "memory");
}
template<int N>
__device__ __forceinline__ void cp_wait() {
    asm volatile("cp.async.wait_group %0;" :: "n"(N) : "memory");
}
__device__ __forceinline__ void ldsm_x4(uint32_t* r, uint32_t addr) {
    asm volatile("ldmatrix.sync.aligned.m8n8.x4.shared.b16 {%0,%1,%2,%3}, [%4];"
                 : "=r"(r[0]), "=r"(r[1]), "=r"(r[2]), "=r"(r[3]) : "r"(addr));
}
__device__ __forceinline__ void mma_f16(float* d, const uint32_t* a,
                                        const uint32_t* b) {
    asm volatile(
        "mma.sync.aligned.m16n8k16.row.col.f32.f16.f16.f32 "
        "{%0,%1,%2,%3}, {%4,%5,%6,%7}, {%8,%9}, {%0,%1,%2,%3};"
        : "+f"(d[0]), "+f"(d[1]), "+f"(d[2]), "+f"(d[3])
        : "r"(a[0]), "r"(a[1]), "r"(a[2]), "r"(a[3]),
          "r"(b[0]), "r"(b[1]));
}
__device__ __forceinline__ float gelu_tanh(float x) {
    float x3 = x * x * x;
    return 0.5f * x * (1.0f + tanhf(0.7978845608028654f * (x + 0.044715f * x3)));
}

// --------------------------- init ------------------------------------------
__global__ void init_kernel() {
    int i = blockIdx.x * blockDim.x + threadIdx.x;
    if (i < MTOT) g_row_src[i] = -1;
    if (i < NTOK * 2) {
        ((int*)g_tok_rows)[i] = -1;
        ((float*)g_tok_g)[i] = 0.0f;
    }
}

// ----------------- router weight transpose [D,E] -> [E,D] -------------------
__global__ void wr_transpose_kernel(const float* __restrict__ wr0,
                                    const float* __restrict__ wr1) {
    int i = blockIdx.x * blockDim.x + threadIdx.x;
    if (i >= DM * NEXP) return;
    int d = i / NEXP, e = i % NEXP;
    g_wrt[0][e * DM + d] = wr0[i];
    g_wrt[1][e * DM + d] = wr1[i];
}

// --------------------------- router ----------------------------------------
__global__ void router_kernel(const float* __restrict__ x,
                              int which, int n_tokens, int tok_base) {
    int gwarp = (blockIdx.x * blockDim.x + threadIdx.x) >> 5;
    int lane  = threadIdx.x & 31;
    if (gwarp >= n_tokens) return;
    const float4* xr = (const float4*)(x + (size_t)gwarp * DM);
    const float* wt = g_wrt[which];

    float acc[NEXP];
#pragma unroll
    for (int e = 0; e < NEXP; e++) acc[e] = 0.f;
#pragma unroll
    for (int it = 0; it < 6; it++) {
        int d4 = it * 32 + lane;
        float4 xv = xr[d4];
#pragma unroll
        for (int e = 0; e < NEXP; e++) {
            float4 wv = ((const float4*)(wt + e * DM))[d4];
            acc[e] += xv.x * wv.x + xv.y * wv.y + xv.z * wv.z + xv.w * wv.w;
        }
    }
#pragma unroll
    for (int e = 0; e < NEXP; e++) {
#pragma unroll
        for (int off = 16; off > 0; off >>= 1)
            acc[e] += __shfl_xor_sync(0xffffffffu, acc[e], off);
    }
    if (lane == 0) {
        float mx = acc[0];
#pragma unroll
        for (int e = 1; e < NEXP; e++) mx = fmaxf(mx, acc[e]);
        float p[NEXP]; float s = 0.f;
#pragma unroll
        for (int e = 0; e < NEXP; e++) { p[e] = expf(acc[e] - mx); s += p[e]; }
        float inv = 1.0f / s;
        int e0 = 0;
#pragma unroll
        for (int e = 1; e < NEXP; e++) if (p[e] > p[e0]) e0 = e;
        int e1 = (e0 == 0) ? 1 : 0;
#pragma unroll
        for (int e = 0; e < NEXP; e++) if (e != e0 && p[e] > p[e1]) e1 = e;
        int t = tok_base + gwarp;
        g_tok_e[t][0] = (signed char)e0;
        g_tok_e[t][1] = (signed char)e1;
        g_tok_p[t][0] = p[e0] * inv;
        g_tok_p[t][1] = p[e1] * inv;
    }
}

// ------------------ positions (rank-major cumsum + capacity) ----------------
__global__ void positions_kernel(int S, int C, int tok_base, int row_off) {
    __shared__ signed char se0[1024], se1[1024];
    __shared__ float sg0[1024], sg1[1024];
    int g = blockIdx.x;
    int tid = threadIdx.x;
    for (int t = tid; t < S; t += blockDim.x) {
        int gt = tok_base + g * S + t;
        se0[t] = g_tok_e[gt][0];
        se1[t] = g_tok_e[gt][1];
        sg0[t] = g_tok_p[gt][0];
        sg1[t] = g_tok_p[gt][1];
    }
    __syncthreads();
    int e = tid >> 5;
    int lane = tid & 31;
    int base = 0;
    int total = 2 * S;
    for (int j0 = 0; j0 < total; j0 += 32) {
        int j = j0 + lane;
        int exp_j = -1;
        if (j < total) exp_j = (j < S) ? (int)se0[j] : (int)se1[j - S];
        bool m = (exp_j == e);
        unsigned mask = __ballot_sync(0xffffffffu, m);
        if (m) {
            int pos = base + __popc(mask & ((1u << lane) - 1u));
            if (pos < C) {
                int t = (j < S) ? j : (j - S);
                int r = (j < S) ? 0 : 1;
                int gt = tok_base + g * S + t;
                float gate = (r == 0) ? sg0[t] : sg1[t];
                int row = e * RPE + row_off + g * C + pos;
                g_row_src[row] = gt;
                g_tok_rows[gt][r] = row;
                g_tok_g[gt][r] = gate;
            }
        }
        base += __popc(mask);
    }
}

// ------------------- weight transpose (fp32 -> half) ------------------------
__global__ void transpose_kernel(const float* __restrict__ src,
                                 __half* __restrict__ dst, int K, int N) {
    __shared__ float tile[32][33];
    int e = blockIdx.z;
    int n0 = blockIdx.x * 32, k0 = blockIdx.y * 32;
    int tx = threadIdx.x, ty = threadIdx.y;
    const float* S = src + (size_t)e * K * N;
    __half* D = dst + (size_t)e * N * K;
#pragma unroll
    for (int r = 0; r < 32; r += 8)
        tile[ty + r][tx] = S[(size_t)(k0 + ty + r) * N + n0 + tx];
    __syncthreads();
#pragma unroll
    for (int r = 0; r < 32; r += 8)
        D[(size_t)(n0 + ty + r) * K + k0 + tx] = __float2half_rn(tile[tx][ty + r]);
}

// --------------------------- gather (fp32 -> half) ---------------------------
__global__ void gather_kernel(const float* __restrict__ xdet,
                              const float* __restrict__ xcls) {
    int row = blockIdx.x;
    int i = threadIdx.x;
    int src = g_row_src[row];
    __half2 h0 = __half2half2(__float2half_rn(0.f));
    __half2 h1 = h0;
    if (src >= 0) {
        const float* xp = (src < NTOK_DET)
            ? (xdet + (size_t)src * DM)
            : (xcls + (size_t)(src - NTOK_DET) * DM);
        float4 v = ((const float4*)xp)[i];
        h0 = __floats2half2_rn(v.x, v.y);
        h1 = __floats2half2_rn(v.z, v.w);
    }
    __half2* dst = (__half2*)(g_xg + (size_t)row * DM) + i * 2;
    dst[0] = h0;
    dst[1] = h1;
}

// --------------------------- mma.sync fp16 GEMM ------------------------------
// 128x128 tile, 256 threads (2 M-warps x 4 N-warps, 64x32 per warp),
// CHUNK=64 halves, cp.async double-buffered, ldmatrix fragment loads.
template<int K, int NTOT, bool GELU, typename OutT>
__device__ __forceinline__ void tc_gemm(const __half* __restrict__ A,
                                        const __half* __restrict__ WT,
                                        const float* __restrict__ bias,
                                        OutT* __restrict__ C) {
    extern __shared__ __half smem[];
    int tid = threadIdx.x;
    int wid = tid >> 5, lane = tid & 31;
    int gid = lane >> 2, tig = lane & 3;
    int warp_m = wid & 1, warp_n = wid >> 1;
    int m_base = warp_m * 64, n_base = warp_n * 32;
    int bx = blockIdx.x, by = blockIdx.y;
    int e = (by * 128) / RPE;
    const __half* Ab = A + (size_t)by * 128 * K;
    const __half* Wb = WT + ((size_t)e * NTOT + (size_t)bx * 128) * K;

    // ldmatrix per-thread offsets (in halves, relative to tile base)
    //   A x4: m0: rows m..m+7 @kk | m1: rows m+8..15 @kk | m2: rows @kk+8 | m3
    //   lanes 0-15 -> rows, lanes 16-31 -> +8 k offset
    uint32_t a_off = (uint32_t)((m_base + (lane & 15)) * SSTR + ((lane >> 4) << 3));
    //   B x4 covers ni pair: rows n..n+7 (@kk, @kk+8), rows n+8..15 (@kk, @kk+8)
    uint32_t b_off = (uint32_t)((n_base + (((lane >> 4) & 1) << 3) + (lane & 7)) * SSTR
                                + (((lane >> 3) & 1) << 3));

    float acc[4][4][4];
#pragma unroll
    for (int mi = 0; mi < 4; mi++)
#pragma unroll
        for (int ni = 0; ni < 4; ni++)
#pragma unroll
            for (int q = 0; q < 4; q++) acc[mi][ni][q] = 0.f;

    const int NC = K / CHUNK;
    uint32_t sbase = smem_u32(smem);

    auto issue_stage = [&](int c) {
        int buf = c & 1;
        uint32_t as = sbase + (uint32_t)(buf * STAGE_HALVES) * 2u;
        uint32_t bs = as + (uint32_t)TILE_HALVES * 2u;
        int kc = c * CHUNK;
#pragma unroll
        for (int j = 0; j < 4; j++) {
            int idx = j * 256 + tid;
            int row = idx >> 3, seg = idx & 7;
            cp_async16(as + (uint32_t)(row * SSTR + seg * 8) * 2u,
                       Ab + (size_t)row * K + kc + seg * 8);
        }
#pragma unroll
        for (int j = 0; j < 4; j++) {
            int idx = j * 256 + tid;
            int row = idx >> 3, seg = idx & 7;
            cp_async16(bs + (uint32_t)(row * SSTR + seg * 8) * 2u,
                       Wb + (size_t)row * K + kc + seg * 8);
        }
        cp_commit();
    };

    issue_stage(0);
    for (int c = 0; c < NC; c++) {
        if (c + 1 < NC) { issue_stage(c + 1); cp_wait<1>(); }
        else            { cp_wait<0>(); }
        __syncthreads();

        uint32_t as = sbase + (uint32_t)((c & 1) * STAGE_HALVES) * 2u;
        uint32_t bs = as + (uint32_t)TILE_HALVES * 2u;
        uint32_t a_base = as + a_off * 2u;
        uint32_t b_base = bs + b_off * 2u;
#pragma unroll
        for (int kk = 0; kk < CHUNK; kk += 16) {
            uint32_t afr[4][4];
#pragma unroll
            for (int mi = 0; mi < 4; mi++)
                ldsm_x4(afr[mi], a_base + (uint32_t)(mi * 16 * SSTR + kk) * 2u);
            uint32_t bfr[2][4];
#pragma unroll
            for (int p = 0; p < 2; p++)
                ldsm_x4(bfr[p], b_base + (uint32_t)(p * 16 * SSTR + kk) * 2u);
#pragma unroll
            for (int mi = 0; mi < 4; mi++)
#pragma unroll
                for (int ni = 0; ni < 4; ni++)
                    mma_f16(acc[mi][ni], afr[mi], &bfr[ni >> 1][(ni & 1) * 2]);
        }
        __syncthreads();
    }

#pragma unroll
    for (int ni = 0; ni < 4; ni++) {
        int cb = bx * 128 + n_base + ni * 8 + 2 * tig;
        float b0 = bias[e * NTOT + cb];
        float b1 = bias[e * NTOT + cb + 1];
#pragma unroll
        for (int mi = 0; mi < 4; mi++) {
            int r0 = by * 128 + m_base + mi * 16 + gid;
            float v0 = acc[mi][ni][0] + b0;
            float v1 = acc[mi][ni][1] + b1;
            float v2 = acc[mi][ni][2] + b0;
            float v3 = acc[mi][ni][3] + b1;
            if (GELU) {
                v0 = gelu_tanh(v0); v1 = gelu_tanh(v1);
                v2 = gelu_tanh(v2); v3 = gelu_tanh(v3);
            }
            OutT* p0 = C + (size_t)r0 * NTOT + cb;
            OutT* p1 = C + (size_t)(r0 + 8) * NTOT + cb;
            if (sizeof(OutT) == 2) {
                *(__half2*)p0 = __floats2half2_rn(v0, v1);
                *(__half2*)p1 = __floats2half2_rn(v2, v3);
            } else {
                *(float2*)p0 = make_float2(v0, v1);
                *(float2*)p1 = make_float2(v2, v3);
            }
        }
    }
}

__global__ __launch_bounds__(256, 2)
void gemm1_tc(const float* __restrict__ b1) {
    tc_gemm<DM, MLPD, true, __half>(g_xg, g_w1t, b1, g_h);
}
__global__ __launch_bounds__(256, 2)
void gemm2_tc(const float* __restrict__ b2) {
    tc_gemm<MLPD, DM, false, float>(g_h, g_w2t, b2, g_ye);
}

// --------------------------- scatter ----------------------------------------
__global__ void scatter_kernel(float* __restrict__ out) {
    int t = blockIdx.x;
    int i = threadIdx.x;
    int r0 = g_tok_rows[t][0];
    int r1 = g_tok_rows[t][1];
    float ga = g_tok_g[t][0];
    float gb = g_tok_g[t][1];
    float4 acc = make_float4(0.f, 0.f, 0.f, 0.f);
    if (r0 >= 0) {
        float4 v = ((const float4*)(g_ye + (size_t)r0 * DM))[i];
        acc.x = ga * v.x; acc.y = ga * v.y; acc.z = ga * v.z; acc.w = ga * v.w;
    }
    if (r1 >= 0) {
        float4 v = ((const float4*)(g_ye + (size_t)r1 * DM))[i];
        acc.x += gb * v.x; acc.y += gb * v.y; acc.z += gb * v.z; acc.w += gb * v.w;
    }
    ((float4*)(out + (size_t)t * DM))[i] = acc;
}

// --------------------------- launch -----------------------------------------
extern "C" void kernel_launch(void* const* d_in, const int* in_sizes, int n_in,
                              void* d_out, int out_size) {
    (void)in_sizes; (void)n_in; (void)out_size;
    const float* xdet = (const float*)d_in[0];
    const float* xcls = (const float*)d_in[1];
    const float* wrd  = (const float*)d_in[2];
    const float* wrc  = (const float*)d_in[3];
    const float* w1   = (const float*)d_in[4];
    const float* b1   = (const float*)d_in[5];
    const float* w2   = (const float*)d_in[6];
    const float* b2   = (const float*)d_in[7];
    float* out = (float*)d_out;

    cudaFuncSetAttribute(gemm1_tc, cudaFuncAttributeMaxDynamicSharedMemorySize, SMEM_DYN);
    cudaFuncSetAttribute(gemm2_tc, cudaFuncAttributeMaxDynamicSharedMemorySize, SMEM_DYN);

    init_kernel<<<(MTOT + 255) / 256, 256>>>();
    wr_transpose_kernel<<<(DM * NEXP + 255) / 256, 256>>>(wrd, wrc);
    {
        __half* w1t; cudaGetSymbolAddress((void**)&w1t, g_w1t);
        __half* w2t; cudaGetSymbolAddress((void**)&w2t, g_w2t);
        transpose_kernel<<<dim3(MLPD / 32, DM / 32, NEXP), dim3(32, 8)>>>(w1, w1t, DM, MLPD);
        transpose_kernel<<<dim3(DM / 32, MLPD / 32, NEXP), dim3(32, 8)>>>(w2, w2t, MLPD, DM);
    }
    router_kernel<<<(NTOK_DET * 32 + 255) / 256, 256>>>(xdet, 0, NTOK_DET, 0);
    router_kernel<<<(NTOK_CLS * 32 + 255) / 256, 256>>>(xcls, 1, NTOK_CLS, NTOK_DET);
    positions_kernel<<<8, 256>>>(1024, CAP_DET, 0, 0);
    positions_kernel<<<8, 256>>>(128, CAP_CLS, NTOK_DET, 2048);
    gather_kernel<<<MTOT, 192>>>(xdet, xcls);
    gemm1_tc<<<dim3(MLPD / 128, MTOT / 128), 256, SMEM_DYN>>>(b1);
    gemm2_tc<<<dim3(DM / 128, MTOT / 128), 256, SMEM_DYN>>>(b2);
    scatter_kernel<<<NTOK, 192>>>(out);
}